// round 16
// baseline (speedup 1.0000x reference)
#include <cuda_runtime.h>
#include <cuda_fp16.h>
#include <math_constants.h>

// EMDLoss (Sinkhorn, eps=0.005, 50 iters), B=8, N=2048, dim=3.
// Morton-sorted sets; log2-domain factored cost. State: single truncated
// lse L[row] (a-units). Fast iterations: per-row fp16 anchor muT_i = L_i,
// ex2.approx.f16x2, clamp +12, fp32 flush every 8 steps. 160-thread blocks
// (20 rows), full-N 32KB table, grid 824 -> 6 blocks/SM, ONE wave.

#define BB 8
#define NN 2048
#define THR 160
#define RPB 20            // rows per block (5 warps x 4)
#define NRG 103           // ceil(2048/20)
#define GRID (BB * NRG)   // 824
#define LOG2N 11.0f

static __device__ float4 d_P4[BB * NN];   // sorted (x,y,z, |p|^2*S2)
static __device__ float4 d_Q4[BB * NN];
static __device__ float  d_Lf[BB * NN];   // truncated lse per P-row (a-units)
static __device__ float  d_Lg[BB * NN];   // truncated lse per Q-row
static __device__ float  d_partials[GRID];

__device__ __forceinline__ float ex2f_(float x) {
    float r; asm("ex2.approx.f32 %0, %1;" : "=f"(r) : "f"(x)); return r;
}
__device__ __forceinline__ float lg2f_(float x) {
    float r; asm("lg2.approx.f32 %0, %1;" : "=f"(r) : "f"(x)); return r;
}

#define S2F      288.5390081777927f      // 1/(eps*ln2)
#define S2X2     577.0780163555854f      // 2/(eps*ln2)
#define EPSLN2   0.0034657359027997f     // eps*ln2
#define EPSLOGMU (-0.03812309493079699f) // eps * (-ln N)
#define TT       25.0f

// ---------------------------------------------------------------------------
__global__ void __launch_bounds__(256) prep_sort_kernel(
    const float* __restrict__ preds, const float* __restrict__ gts) {
    int blk = blockIdx.x;
    int b = blk >> 1;
    int set = blk & 1;
    const float* src = set ? gts : preds;
    float4* dst = set ? d_Q4 : d_P4;
    int off = b * NN;

    __shared__ unsigned skey[NN];

    for (int i = threadIdx.x; i < NN; i += 256) {
        const float* p = src + (off + i) * 3;
        float x = p[0], y = p[1], z = p[2];
        int ux = (int)floorf((x + 4.f) * 4.f); ux = min(31, max(0, ux));
        int uy = (int)floorf((y + 4.f) * 4.f); uy = min(31, max(0, uy));
        int uz = (int)floorf((z + 4.f) * 4.f); uz = min(31, max(0, uz));
        unsigned key = 0;
#pragma unroll
        for (int bit = 0; bit < 5; ++bit) {
            key |= (((unsigned)ux >> bit) & 1u) << (3 * bit + 2);
            key |= (((unsigned)uy >> bit) & 1u) << (3 * bit + 1);
            key |= (((unsigned)uz >> bit) & 1u) << (3 * bit + 0);
        }
        skey[i] = (key << 11) | (unsigned)i;
    }
    __syncthreads();

    for (int k = 2; k <= NN; k <<= 1) {
        for (int j = k >> 1; j > 0; j >>= 1) {
            for (int i = threadIdx.x; i < NN; i += 256) {
                int l = i ^ j;
                if (l > i) {
                    unsigned a = skey[i], c = skey[l];
                    bool up = ((i & k) == 0);
                    if ((a > c) == up) { skey[i] = c; skey[l] = a; }
                }
            }
            __syncthreads();
        }
    }

    for (int i = threadIdx.x; i < NN; i += 256) {
        int si = (int)(skey[i] & 2047u);
        const float* p = src + (off + si) * 3;
        float x = p[0], y = p[1], z = p[2];
        dst[off + i] = make_float4(x, y, z, (x * x + y * y + z * z) * S2F);
    }
}

// ---------------------------------------------------------------------------
// Decode: grid = BB * NRG; clamp last rowgroup's warps (idempotent writes).
#define DECODE_BLK()                                                \
    int blk = blockIdx.x;                                           \
    int b = blk / NRG;                                              \
    int rg = blk - b * NRG;                                         \
    int off = b * NN;                                               \
    int warp = threadIdx.x >> 5;                                    \
    int lane = threadIdx.x & 31;                                    \
    int rnom = rg * RPB + warp * 4;                                 \
    int row0 = off + min(rnom, NN - 4);

#define MERGEROW(m, s, off)                                         \
    {                                                               \
        float mo = __shfl_xor_sync(0xffffffffu, m, off);            \
        float so = __shfl_xor_sync(0xffffffffu, s, off);            \
        float mn = fmaxf(m, mo);                                    \
        s = fmaf(so, ex2f_(mo - mn), s * ex2f_(m - mn));            \
        m = mn;                                                     \
    }

#define ROWUPD(m, s, mt, a, e)                                      \
    if (__any_sync(0xffffffffu, (e) > 0.f)) {                       \
        if (__any_sync(0xffffffffu, (a) > (m))) {                   \
            float c = fmaxf(m, a);                                  \
            c = fmaxf(c, __shfl_xor_sync(0xffffffffu, c, 16));      \
            c = fmaxf(c, __shfl_xor_sync(0xffffffffu, c, 8));       \
            c = fmaxf(c, __shfl_xor_sync(0xffffffffu, c, 4));       \
            c = fmaxf(c, __shfl_xor_sync(0xffffffffu, c, 2));       \
            c = fmaxf(c, __shfl_xor_sync(0xffffffffu, c, 1));       \
            s = fmaf(s, ex2f_(m - c), ex2f_((a) - c));              \
            m = c; mt = c - TT;                                     \
        } else {                                                    \
            s += ex2f_((a) - m);                                    \
        }                                                           \
    }

// Boot (iteration 0): full-table fp32 online LSE; stores L.
__global__ void __launch_bounds__(THR, 6) half_boot(int dir) {
    DECODE_BLK();

    const float4* R4 = dir ? d_Q4 : d_P4;
    const float4* D4 = dir ? d_P4 : d_Q4;
    float* rL = dir ? d_Lg : d_Lf;

    __shared__ float4 tbl[NN];
    for (int t = threadIdx.x; t < NN; t += THR) {
        int j = off + t;
        float4 q = D4[j];
        float4 tt;
        tt.x = q.x * S2X2;
        tt.y = q.y * S2X2;
        tt.z = q.z * S2X2;
        tt.w = dir ? (-LOG2N - d_Lf[j]) : -q.w;   // pot*S2 - qq*S2
        tbl[t] = tt;
    }
    __syncthreads();

    float4 r0 = R4[row0 + 0];
    float4 r1 = R4[row0 + 1];
    float4 r2 = R4[row0 + 2];
    float4 r3 = R4[row0 + 3];

    const float NEGINF = -CUDART_INF_F;
    float m0 = NEGINF, m1 = NEGINF, m2 = NEGINF, m3 = NEGINF;
    float s0 = 0.f, s1 = 0.f, s2 = 0.f, s3 = 0.f;
    float mt0 = NEGINF, mt1 = NEGINF, mt2 = NEGINF, mt3 = NEGINF;

#pragma unroll 2
    for (int k = 0; k < 64; ++k) {
        float4 q = tbl[(k << 5) + lane];
        float a0 = fmaf(r0.x, q.x, fmaf(r0.y, q.y, fmaf(r0.z, q.z, q.w)));
        float a1 = fmaf(r1.x, q.x, fmaf(r1.y, q.y, fmaf(r1.z, q.z, q.w)));
        float a2 = fmaf(r2.x, q.x, fmaf(r2.y, q.y, fmaf(r2.z, q.z, q.w)));
        float a3 = fmaf(r3.x, q.x, fmaf(r3.y, q.y, fmaf(r3.z, q.z, q.w)));
        float e0 = a0 - mt0;
        float e1 = a1 - mt1;
        float e2 = a2 - mt2;
        float e3 = a3 - mt3;
        float emax = fmaxf(fmaxf(e0, e1), fmaxf(e2, e3));
        if (__any_sync(0xffffffffu, emax > 0.f)) {
            ROWUPD(m0, s0, mt0, a0, e0)
            ROWUPD(m1, s1, mt1, a1, e1)
            ROWUPD(m2, s2, mt2, a2, e2)
            ROWUPD(m3, s3, mt3, a3, e3)
        }
    }

#pragma unroll
    for (int o = 16; o; o >>= 1) {
        MERGEROW(m0, s0, o);
        MERGEROW(m1, s1, o);
        MERGEROW(m2, s2, o);
        MERGEROW(m3, s3, o);
    }

    if (lane == 0) {
        rL[row0 + 0] = m0 + lg2f_(s0);
        rL[row0 + 1] = m1 + lg2f_(s1);
        rL[row0 + 2] = m2 + lg2f_(s2);
        rL[row0 + 3] = m3 + lg2f_(s3);
    }
}

// ---------------------------------------------------------------------------
// Fast half-update: per-row anchor muT_i = L_i; fp16x2 exponentials.
__global__ void __launch_bounds__(THR, 6) half_fast(int dir) {
    DECODE_BLK();

    const float4* R4 = dir ? d_Q4 : d_P4;
    const float4* D4 = dir ? d_P4 : d_Q4;
    const float* tL = dir ? d_Lf : d_Lg;
    float* rL = dir ? d_Lg : d_Lf;

    __shared__ float4 tbl[NN];
    for (int t = threadIdx.x; t < NN; t += THR) {
        int j = off + t;
        float4 q = D4[j];
        float4 tt;
        tt.x = q.x * S2X2;
        tt.y = q.y * S2X2;
        tt.z = q.z * S2X2;
        tt.w = -LOG2N - tL[j];   // pot*S2 - qq*S2
        tbl[t] = tt;
    }
    __syncthreads();

    float4 r0 = R4[row0 + 0];
    float4 r1 = R4[row0 + 1];
    float4 r2 = R4[row0 + 2];
    float4 r3 = R4[row0 + 3];

    // per-row anchor = previous lse (max term ~2^0 always survives fp16)
    float muT0 = rL[row0 + 0];
    float muT1 = rL[row0 + 1];
    float muT2 = rL[row0 + 2];
    float muT3 = rL[row0 + 3];

    const __half2 clampv = __float2half2_rn(12.f);
    float s0 = 1e-9f, s1 = 1e-9f, s2 = 1e-9f, s3 = 1e-9f;  // lg2(0) guard

#pragma unroll
    for (int kk = 0; kk < 8; ++kk) {
        __half2 acc01 = __float2half2_rn(0.f);
        __half2 acc23 = __float2half2_rn(0.f);
#pragma unroll
        for (int k2 = 0; k2 < 8; ++k2) {
            int k = (kk << 3) + k2;
            float4 q = tbl[(k << 5) + lane];
            float a0 = fmaf(r0.x, q.x, fmaf(r0.y, q.y, fmaf(r0.z, q.z, q.w)));
            float a1 = fmaf(r1.x, q.x, fmaf(r1.y, q.y, fmaf(r1.z, q.z, q.w)));
            float a2 = fmaf(r2.x, q.x, fmaf(r2.y, q.y, fmaf(r2.z, q.z, q.w)));
            float a3 = fmaf(r3.x, q.x, fmaf(r3.y, q.y, fmaf(r3.z, q.z, q.w)));
            __half2 h01 = __hmin2(__floats2half2_rn(a0 - muT0, a1 - muT1), clampv);
            __half2 h23 = __hmin2(__floats2half2_rn(a2 - muT2, a3 - muT3), clampv);
            acc01 = __hadd2(acc01, h2exp2(h01));
            acc23 = __hadd2(acc23, h2exp2(h23));
        }
        float2 f01 = __half22float2(acc01);
        float2 f23 = __half22float2(acc23);
        s0 += f01.x; s1 += f01.y;
        s2 += f23.x; s3 += f23.y;
    }

#pragma unroll
    for (int o = 16; o; o >>= 1) {
        s0 += __shfl_xor_sync(0xffffffffu, s0, o);
        s1 += __shfl_xor_sync(0xffffffffu, s1, o);
        s2 += __shfl_xor_sync(0xffffffffu, s2, o);
        s3 += __shfl_xor_sync(0xffffffffu, s3, o);
    }

    if (lane == 0) {
        rL[row0 + 0] = muT0 + lg2f_(s0);   // new truncated lse
        rL[row0 + 1] = muT1 + lg2f_(s1);
        rL[row0 + 2] = muT2 + lg2f_(s2);
        rL[row0 + 3] = muT3 + lg2f_(s3);
    }
}

// ---------------------------------------------------------------------------
// Loss: full table, fp32; duplicated (clamped) warps contribute zero.
__global__ void __launch_bounds__(THR, 6) loss_kernel() {
    DECODE_BLK();

    __shared__ float4 tbl[NN];
    __shared__ float  gg[NN];
    for (int t = threadIdx.x; t < NN; t += THR) {
        int j = off + t;
        float4 q = d_Q4[j];
        float L = d_Lg[j];
        float4 tt;
        tt.x = q.x * S2X2;
        tt.y = q.y * S2X2;
        tt.z = q.z * S2X2;
        tt.w = -LOG2N - L;
        tbl[t] = tt;
        gg[t] = fmaf(-EPSLN2, L - q.w, EPSLOGMU);   // g_j
    }
    __syncthreads();

    float valid = (rnom <= NN - 4) ? 1.f : 0.f;   // duplicated warps -> 0

    float4 r0 = d_P4[row0 + 0];
    float4 r1 = d_P4[row0 + 1];
    float4 r2 = d_P4[row0 + 2];
    float4 r3 = d_P4[row0 + 3];

    float lf0 = d_Lf[row0 + 0];
    float lf1 = d_Lf[row0 + 1];
    float lf2 = d_Lf[row0 + 2];
    float lf3 = d_Lf[row0 + 3];

    float fr0 = fmaf(-EPSLN2, lf0 - r0.w, EPSLOGMU);
    float fr1 = fmaf(-EPSLN2, lf1 - r1.w, EPSLOGMU);
    float fr2 = fmaf(-EPSLN2, lf2 - r2.w, EPSLOGMU);
    float fr3 = fmaf(-EPSLN2, lf3 - r3.w, EPSLOGMU);

    float ff0 = -LOG2N - lf0;   // f*S2 - pp*S2
    float ff1 = -LOG2N - lf1;
    float ff2 = -LOG2N - lf2;
    float ff3 = -LOG2N - lf3;

    float part = 0.f;
#pragma unroll 4
    for (int k = 0; k < 64; ++k) {
        int j = (k << 5) + lane;
        float4 q = tbl[j];
        float gj = gg[j];
        {
            float a = fmaf(r0.x, q.x, fmaf(r0.y, q.y, fmaf(r0.z, q.z, q.w)));
            float arg = a + ff0;
            float C = fmaf(-EPSLN2, arg, fr0 + gj);
            part = fmaf(ex2f_(arg), C, part);
        }
        {
            float a = fmaf(r1.x, q.x, fmaf(r1.y, q.y, fmaf(r1.z, q.z, q.w)));
            float arg = a + ff1;
            float C = fmaf(-EPSLN2, arg, fr1 + gj);
            part = fmaf(ex2f_(arg), C, part);
        }
        {
            float a = fmaf(r2.x, q.x, fmaf(r2.y, q.y, fmaf(r2.z, q.z, q.w)));
            float arg = a + ff2;
            float C = fmaf(-EPSLN2, arg, fr2 + gj);
            part = fmaf(ex2f_(arg), C, part);
        }
        {
            float a = fmaf(r3.x, q.x, fmaf(r3.y, q.y, fmaf(r3.z, q.z, q.w)));
            float arg = a + ff3;
            float C = fmaf(-EPSLN2, arg, fr3 + gj);
            part = fmaf(ex2f_(arg), C, part);
        }
    }
    part *= valid;

    __shared__ float red[THR];
    red[threadIdx.x] = part;
    __syncthreads();
    if (threadIdx.x < 32) {       // 160 = 32 x 5
        float v = red[threadIdx.x];
#pragma unroll
        for (int w = 1; w < 5; ++w) v += red[threadIdx.x + 32 * w];
#pragma unroll
        for (int o = 16; o; o >>= 1)
            v += __shfl_xor_sync(0xffffffffu, v, o);
        if (threadIdx.x == 0) d_partials[blockIdx.x] = v;
    }
}

__global__ void reduce_kernel(float* __restrict__ out) {
    __shared__ float red[256];
    float v = 0.f;
    for (int i = threadIdx.x; i < GRID; i += 256) v += d_partials[i];
    red[threadIdx.x] = v;
    __syncthreads();
#pragma unroll
    for (int o = 128; o; o >>= 1) {
        if (threadIdx.x < o) red[threadIdx.x] += red[threadIdx.x + o];
        __syncthreads();
    }
    if (threadIdx.x == 0) out[0] = red[0] * 0.125f;
}

extern "C" void kernel_launch(void* const* d_in, const int* in_sizes, int n_in,
                              void* d_out, int out_size) {
    const float* preds = (const float*)d_in[0];
    const float* gts   = (const float*)d_in[1];
    float* out = (float*)d_out;

    prep_sort_kernel<<<BB * 2, 256>>>(preds, gts);
    half_boot<<<GRID, THR>>>(0);
    half_boot<<<GRID, THR>>>(1);
    for (int it = 1; it < 50; ++it) {
        half_fast<<<GRID, THR>>>(0);
        half_fast<<<GRID, THR>>>(1);
    }
    loss_kernel<<<GRID, THR>>>();
    reduce_kernel<<<1, 256>>>(out);
}

// round 17
// speedup vs baseline: 1.2154x; 1.2154x over previous
#include <cuda_runtime.h>
#include <cuda_fp16.h>
#include <math_constants.h>

// EMDLoss (Sinkhorn, eps=0.005, 50 iters), B=8, N=2048, dim=3.
// R12 structure (best: grid 1024, j-half split, fp16x2 exponentials,
// per-row anchor muT_i = prev lse) with half_fast forced to 32 regs via
// __launch_bounds__(256, 8): 8 blocks/SM -> capacity 1184 >= grid 1024 ->
// ONE wave at 86% fill (R12 ran 2 waves, 2nd 38% full). r.w rematerialized
// after the loop so only r.xyz stays live through the inner loop.

#define BB 8
#define NN 2048
#define LOG2N 11.0f

static __device__ float4 d_P4[BB * NN];     // sorted (x,y,z, |p|^2*S2)
static __device__ float4 d_Q4[BB * NN];
static __device__ float  d_LP[2][BB * NN];  // per-half truncated lse (a-units)
static __device__ float  d_LQ[2][BB * NN];
static __device__ float  d_partials[1024];

__device__ __forceinline__ float ex2f_(float x) {
    float r; asm("ex2.approx.f32 %0, %1;" : "=f"(r) : "f"(x)); return r;
}
__device__ __forceinline__ float lg2f_(float x) {
    float r; asm("lg2.approx.f32 %0, %1;" : "=f"(r) : "f"(x)); return r;
}
// combine two half-lse values (log2 domain).
__device__ __forceinline__ float comb2_(float L0, float L1) {
    float m = fmaxf(L0, L1);
    float n = fminf(L0, L1);
    return m + lg2f_(1.f + ex2f_(n - m));
}

#define S2F      288.5390081777927f      // 1/(eps*ln2)
#define S2X2     577.0780163555854f      // 2/(eps*ln2)
#define EPSLN2   0.0034657359027997f     // eps*ln2
#define EPSLOGMU (-0.03812309493079699f) // eps * (-ln N)
#define TT       25.0f

// ---------------------------------------------------------------------------
__global__ void __launch_bounds__(256) prep_sort_kernel(
    const float* __restrict__ preds, const float* __restrict__ gts) {
    int blk = blockIdx.x;
    int b = blk >> 1;
    int set = blk & 1;
    const float* src = set ? gts : preds;
    float4* dst = set ? d_Q4 : d_P4;
    int off = b * NN;

    __shared__ unsigned skey[NN];

    for (int i = threadIdx.x; i < NN; i += 256) {
        const float* p = src + (off + i) * 3;
        float x = p[0], y = p[1], z = p[2];
        int ux = (int)floorf((x + 4.f) * 4.f); ux = min(31, max(0, ux));
        int uy = (int)floorf((y + 4.f) * 4.f); uy = min(31, max(0, uy));
        int uz = (int)floorf((z + 4.f) * 4.f); uz = min(31, max(0, uz));
        unsigned key = 0;
#pragma unroll
        for (int bit = 0; bit < 5; ++bit) {
            key |= (((unsigned)ux >> bit) & 1u) << (3 * bit + 2);
            key |= (((unsigned)uy >> bit) & 1u) << (3 * bit + 1);
            key |= (((unsigned)uz >> bit) & 1u) << (3 * bit + 0);
        }
        skey[i] = (key << 11) | (unsigned)i;
    }
    __syncthreads();

    for (int k = 2; k <= NN; k <<= 1) {
        for (int j = k >> 1; j > 0; j >>= 1) {
            for (int i = threadIdx.x; i < NN; i += 256) {
                int l = i ^ j;
                if (l > i) {
                    unsigned a = skey[i], c = skey[l];
                    bool up = ((i & k) == 0);
                    if ((a > c) == up) { skey[i] = c; skey[l] = a; }
                }
            }
            __syncthreads();
        }
    }

    for (int i = threadIdx.x; i < NN; i += 256) {
        int si = (int)(skey[i] & 2047u);
        const float* p = src + (off + si) * 3;
        float x = p[0], y = p[1], z = p[2];
        dst[off + i] = make_float4(x, y, z, (x * x + y * y + z * z) * S2F);
    }
}

// ---------------------------------------------------------------------------
// Common decode: grid = BB * 64 rowgroups * 2 j-halves.
#define DECODE_BLK()                                                \
    int blk = blockIdx.x;                                           \
    int b = blk >> 7;                                               \
    int rest = blk & 127;                                           \
    int rg = rest >> 1;                                             \
    int half = rest & 1;                                            \
    int off = b * NN;

#define MERGEROW(m, s, off)                                         \
    {                                                               \
        float mo = __shfl_xor_sync(0xffffffffu, m, off);            \
        float so = __shfl_xor_sync(0xffffffffu, s, off);            \
        float mn = fmaxf(m, mo);                                    \
        s = fmaf(so, ex2f_(mo - mn), s * ex2f_(m - mn));            \
        m = mn;                                                     \
    }

#define ROWUPD(m, s, mt, a, e)                                      \
    if (__any_sync(0xffffffffu, (e) > 0.f)) {                       \
        if (__any_sync(0xffffffffu, (a) > (m))) {                   \
            float c = fmaxf(m, a);                                  \
            c = fmaxf(c, __shfl_xor_sync(0xffffffffu, c, 16));      \
            c = fmaxf(c, __shfl_xor_sync(0xffffffffu, c, 8));       \
            c = fmaxf(c, __shfl_xor_sync(0xffffffffu, c, 4));       \
            c = fmaxf(c, __shfl_xor_sync(0xffffffffu, c, 2));       \
            c = fmaxf(c, __shfl_xor_sync(0xffffffffu, c, 1));       \
            s = fmaf(s, ex2f_(m - c), ex2f_((a) - c));              \
            m = c; mt = c - TT;                                     \
        } else {                                                    \
            s += ex2f_((a) - m);                                    \
        }                                                           \
    }

// Boot half-update (iteration 0): fp32 online LSE over this j-half; stores L.
__global__ void __launch_bounds__(256) half_boot(int dir) {
    DECODE_BLK();

    const float4* R4 = dir ? d_Q4 : d_P4;
    const float4* D4 = dir ? d_P4 : d_Q4;
    float* rL = dir ? d_LQ[half] : d_LP[half];

    __shared__ float4 tbl[NN / 2];
    for (int t = threadIdx.x; t < NN / 2; t += 256) {
        int j = off + (half << 10) + t;
        float4 q = D4[j];
        float4 tt;
        tt.x = q.x * S2X2;
        tt.y = q.y * S2X2;
        tt.z = q.z * S2X2;
        tt.w = dir ? (-LOG2N - comb2_(d_LP[0][j], d_LP[1][j])) : -q.w;
        tbl[t] = tt;
    }
    __syncthreads();

    int warp = threadIdx.x >> 5;
    int lane = threadIdx.x & 31;
    int row0 = off + rg * 32 + warp * 4;

    float4 r0 = R4[row0 + 0];
    float4 r1 = R4[row0 + 1];
    float4 r2 = R4[row0 + 2];
    float4 r3 = R4[row0 + 3];

    const float NEGINF = -CUDART_INF_F;
    float m0 = NEGINF, m1 = NEGINF, m2 = NEGINF, m3 = NEGINF;
    float s0 = 0.f, s1 = 0.f, s2 = 0.f, s3 = 0.f;
    float mt0 = NEGINF, mt1 = NEGINF, mt2 = NEGINF, mt3 = NEGINF;

#pragma unroll 2
    for (int k = 0; k < 32; ++k) {
        float4 q = tbl[(k << 5) + lane];
        float a0 = fmaf(r0.x, q.x, fmaf(r0.y, q.y, fmaf(r0.z, q.z, q.w)));
        float a1 = fmaf(r1.x, q.x, fmaf(r1.y, q.y, fmaf(r1.z, q.z, q.w)));
        float a2 = fmaf(r2.x, q.x, fmaf(r2.y, q.y, fmaf(r2.z, q.z, q.w)));
        float a3 = fmaf(r3.x, q.x, fmaf(r3.y, q.y, fmaf(r3.z, q.z, q.w)));
        float e0 = a0 - mt0;
        float e1 = a1 - mt1;
        float e2 = a2 - mt2;
        float e3 = a3 - mt3;
        float emax = fmaxf(fmaxf(e0, e1), fmaxf(e2, e3));
        if (__any_sync(0xffffffffu, emax > 0.f)) {
            ROWUPD(m0, s0, mt0, a0, e0)
            ROWUPD(m1, s1, mt1, a1, e1)
            ROWUPD(m2, s2, mt2, a2, e2)
            ROWUPD(m3, s3, mt3, a3, e3)
        }
    }

#pragma unroll
    for (int o = 16; o; o >>= 1) {
        MERGEROW(m0, s0, o);
        MERGEROW(m1, s1, o);
        MERGEROW(m2, s2, o);
        MERGEROW(m3, s3, o);
    }

    if (lane == 0) {
        rL[row0 + 0] = m0 + lg2f_(s0);
        rL[row0 + 1] = m1 + lg2f_(s1);
        rL[row0 + 2] = m2 + lg2f_(s2);
        rL[row0 + 3] = m3 + lg2f_(s3);
    }
}

// ---------------------------------------------------------------------------
// Fast half-update: per-row anchor (muT_i = prev lse), fp16x2 exponentials.
// Forced to 8 blocks/SM (<=32 regs) -> grid 1024 fits in ONE wave.
__global__ void __launch_bounds__(256, 8) half_fast(int dir) {
    DECODE_BLK();

    const float4* R4 = dir ? d_Q4 : d_P4;
    const float4* D4 = dir ? d_P4 : d_Q4;
    const float* tL0 = dir ? d_LP[0] : d_LQ[0];
    const float* tL1 = dir ? d_LP[1] : d_LQ[1];
    const float* rLA = dir ? d_LQ[0] : d_LP[0];
    const float* rLB = dir ? d_LQ[1] : d_LP[1];
    float* rL = dir ? d_LQ[half] : d_LP[half];

    __shared__ float4 tbl[NN / 2];
    for (int t = threadIdx.x; t < NN / 2; t += 256) {
        int j = off + (half << 10) + t;
        float4 q = D4[j];
        float4 tt;
        tt.x = q.x * S2X2;
        tt.y = q.y * S2X2;
        tt.z = q.z * S2X2;
        tt.w = -LOG2N - comb2_(tL0[j], tL1[j]);   // pot*S2 - qq*S2
        tbl[t] = tt;
    }
    __syncthreads();

    int warp = threadIdx.x >> 5;
    int lane = threadIdx.x & 31;
    int row0 = off + rg * 32 + warp * 4;

    // load only xyz into loop-live registers (w rematerialized after loop)
    float3 r0, r1, r2, r3;
    {
        float4 t0 = R4[row0 + 0]; r0 = make_float3(t0.x, t0.y, t0.z);
        float4 t1 = R4[row0 + 1]; r1 = make_float3(t1.x, t1.y, t1.z);
        float4 t2 = R4[row0 + 2]; r2 = make_float3(t2.x, t2.y, t2.z);
        float4 t3 = R4[row0 + 3]; r3 = make_float3(t3.x, t3.y, t3.z);
    }

    // per-row anchor = previous full lse (max term ~2^0 always survives fp16)
    float muT0 = fmaxf(rLA[row0 + 0], rLB[row0 + 0]);
    float muT1 = fmaxf(rLA[row0 + 1], rLB[row0 + 1]);
    float muT2 = fmaxf(rLA[row0 + 2], rLB[row0 + 2]);
    float muT3 = fmaxf(rLA[row0 + 3], rLB[row0 + 3]);

    const __half2 clampv = __float2half2_rn(12.f);
    float s0 = 1e-9f, s1 = 1e-9f, s2 = 1e-9f, s3 = 1e-9f;  // lg2(0) guard

#pragma unroll
    for (int kk = 0; kk < 4; ++kk) {
        __half2 acc01 = __float2half2_rn(0.f);
        __half2 acc23 = __float2half2_rn(0.f);
#pragma unroll
        for (int k2 = 0; k2 < 8; ++k2) {
            int k = (kk << 3) + k2;
            float4 q = tbl[(k << 5) + lane];
            float a0 = fmaf(r0.x, q.x, fmaf(r0.y, q.y, fmaf(r0.z, q.z, q.w)));
            float a1 = fmaf(r1.x, q.x, fmaf(r1.y, q.y, fmaf(r1.z, q.z, q.w)));
            float a2 = fmaf(r2.x, q.x, fmaf(r2.y, q.y, fmaf(r2.z, q.z, q.w)));
            float a3 = fmaf(r3.x, q.x, fmaf(r3.y, q.y, fmaf(r3.z, q.z, q.w)));
            __half2 h01 = __hmin2(__floats2half2_rn(a0 - muT0, a1 - muT1), clampv);
            __half2 h23 = __hmin2(__floats2half2_rn(a2 - muT2, a3 - muT3), clampv);
            acc01 = __hadd2(acc01, h2exp2(h01));
            acc23 = __hadd2(acc23, h2exp2(h23));
        }
        float2 f01 = __half22float2(acc01);
        float2 f23 = __half22float2(acc23);
        s0 += f01.x; s1 += f01.y;
        s2 += f23.x; s3 += f23.y;
    }

#pragma unroll
    for (int o = 16; o; o >>= 1) {
        s0 += __shfl_xor_sync(0xffffffffu, s0, o);
        s1 += __shfl_xor_sync(0xffffffffu, s1, o);
        s2 += __shfl_xor_sync(0xffffffffu, s2, o);
        s3 += __shfl_xor_sync(0xffffffffu, s3, o);
    }

    if (lane == 0) {
        rL[row0 + 0] = muT0 + lg2f_(s0);   // truncated half-lse
        rL[row0 + 1] = muT1 + lg2f_(s1);
        rL[row0 + 2] = muT2 + lg2f_(s2);
        rL[row0 + 3] = muT3 + lg2f_(s3);
    }
}

// ---------------------------------------------------------------------------
// Loss: 4 rows/thread, branch-free fp32; reconstruct f and g from L arrays.
__global__ void __launch_bounds__(256) loss_kernel() {
    DECODE_BLK();

    __shared__ float4 tbl[NN / 2];
    __shared__ float  gg[NN / 2];
    for (int t = threadIdx.x; t < NN / 2; t += 256) {
        int j = off + (half << 10) + t;
        float4 q = d_Q4[j];
        float lse = comb2_(d_LQ[0][j], d_LQ[1][j]);
        float4 tt;
        tt.x = q.x * S2X2;
        tt.y = q.y * S2X2;
        tt.z = q.z * S2X2;
        tt.w = -LOG2N - lse;
        tbl[t] = tt;
        gg[t] = fmaf(-EPSLN2, lse - q.w, EPSLOGMU);   // g_j
    }
    __syncthreads();

    int warp = threadIdx.x >> 5;
    int lane = threadIdx.x & 31;
    int row0 = off + rg * 32 + warp * 4;

    float4 r0 = d_P4[row0 + 0];
    float4 r1 = d_P4[row0 + 1];
    float4 r2 = d_P4[row0 + 2];
    float4 r3 = d_P4[row0 + 3];

    float lf0 = comb2_(d_LP[0][row0 + 0], d_LP[1][row0 + 0]);
    float lf1 = comb2_(d_LP[0][row0 + 1], d_LP[1][row0 + 1]);
    float lf2 = comb2_(d_LP[0][row0 + 2], d_LP[1][row0 + 2]);
    float lf3 = comb2_(d_LP[0][row0 + 3], d_LP[1][row0 + 3]);

    float fr0 = fmaf(-EPSLN2, lf0 - r0.w, EPSLOGMU);
    float fr1 = fmaf(-EPSLN2, lf1 - r1.w, EPSLOGMU);
    float fr2 = fmaf(-EPSLN2, lf2 - r2.w, EPSLOGMU);
    float fr3 = fmaf(-EPSLN2, lf3 - r3.w, EPSLOGMU);

    float ff0 = -LOG2N - lf0;   // f*S2 - pp*S2
    float ff1 = -LOG2N - lf1;
    float ff2 = -LOG2N - lf2;
    float ff3 = -LOG2N - lf3;

    float part = 0.f;
#pragma unroll 4
    for (int k = 0; k < 32; ++k) {
        int j = (k << 5) + lane;
        float4 q = tbl[j];
        float gj = gg[j];
        {
            float a = fmaf(r0.x, q.x, fmaf(r0.y, q.y, fmaf(r0.z, q.z, q.w)));
            float arg = a + ff0;
            float C = fmaf(-EPSLN2, arg, fr0 + gj);
            part = fmaf(ex2f_(arg), C, part);
        }
        {
            float a = fmaf(r1.x, q.x, fmaf(r1.y, q.y, fmaf(r1.z, q.z, q.w)));
            float arg = a + ff1;
            float C = fmaf(-EPSLN2, arg, fr1 + gj);
            part = fmaf(ex2f_(arg), C, part);
        }
        {
            float a = fmaf(r2.x, q.x, fmaf(r2.y, q.y, fmaf(r2.z, q.z, q.w)));
            float arg = a + ff2;
            float C = fmaf(-EPSLN2, arg, fr2 + gj);
            part = fmaf(ex2f_(arg), C, part);
        }
        {
            float a = fmaf(r3.x, q.x, fmaf(r3.y, q.y, fmaf(r3.z, q.z, q.w)));
            float arg = a + ff3;
            float C = fmaf(-EPSLN2, arg, fr3 + gj);
            part = fmaf(ex2f_(arg), C, part);
        }
    }

    __shared__ float red[256];
    red[threadIdx.x] = part;
    __syncthreads();
#pragma unroll
    for (int o = 128; o; o >>= 1) {
        if (threadIdx.x < o) red[threadIdx.x] += red[threadIdx.x + o];
        __syncthreads();
    }
    if (threadIdx.x == 0) d_partials[blockIdx.x] = red[0];
}

__global__ void reduce_kernel(float* __restrict__ out) {
    __shared__ float red[256];
    float v = 0.f;
    for (int i = threadIdx.x; i < 1024; i += 256) v += d_partials[i];
    red[threadIdx.x] = v;
    __syncthreads();
#pragma unroll
    for (int o = 128; o; o >>= 1) {
        if (threadIdx.x < o) red[threadIdx.x] += red[threadIdx.x + o];
        __syncthreads();
    }
    if (threadIdx.x == 0) out[0] = red[0] * 0.125f;
}

extern "C" void kernel_launch(void* const* d_in, const int* in_sizes, int n_in,
                              void* d_out, int out_size) {
    const float* preds = (const float*)d_in[0];
    const float* gts   = (const float*)d_in[1];
    float* out = (float*)d_out;

    prep_sort_kernel<<<BB * 2, 256>>>(preds, gts);
    half_boot<<<BB * 128, 256>>>(0);
    half_boot<<<BB * 128, 256>>>(1);
    for (int it = 1; it < 50; ++it) {
        half_fast<<<BB * 128, 256>>>(0);
        half_fast<<<BB * 128, 256>>>(1);
    }
    loss_kernel<<<BB * 128, 256>>>();
    reduce_kernel<<<1, 256>>>(out);
}